// round 14
// baseline (speedup 1.0000x reference)
#include <cuda_runtime.h>
#include <cuda_bf16.h>

// HMM forward DP (softmax semiring), strip-pipelined wavefront.
// theta: (2048, 2048, 3) f32, A: (3,3) f32, out: scalar f32.
//
// R13: R11-identical numerics (natural log, __logf/__expf, flag handshake)
// + diagonal-major theta (coalesced DP loads)
// + one flag per private 128B line (no cross-pair L2 line contention)
// + speculative flag prefetch (acquire latency overlapped with compute)
// + 8-deep software pipeline.

#define NEG_INF   (-1.0e8f)
#define NDIM      2048
#define MCOLS     2048
#define HROWS     32
#define NBLK      (NDIM / HROWS)        /* 64 */
#define DROWS     4112                  /* padded diagonal count (covers prefetch overrun) */

// diagonal-major theta: gThD[((d-2)*2048 + (row-1))*3 + s]   (~101 MB, zeros where invalid)
__device__ float  gThD[DROWS * MCOLS * 3];
// handoff: bottom-row results of each strip, (m, e0, e1, e2) per column j in [1,2048]
__device__ float4 gHand[NBLK][MCOLS + 16];
// one progress flag per 128-byte line: exactly 1 writer + 1 reader per line
__device__ int    gProg2[NBLK][32];
__device__ float  gB[9];                // exp(A[s][k])

// ---------------------------------------------------------------- pre-passes

__global__ void diagize(const float* __restrict__ theta) {
    int idx = blockIdx.x * blockDim.x + threadIdx.x;   // [0, DROWS*2048)
    if (idx >= DROWS * MCOLS) return;
    int dm2 = idx >> 11;          // d - 2
    int im1 = idx & 2047;         // row - 1
    int j   = dm2 + 1 - im1;      // col = d - row
    float a = 0.f, b = 0.f, c = 0.f;
    if (j >= 1 && j <= MCOLS) {
        int s = (im1 * MCOLS + (j - 1)) * 3;
        a = theta[s]; b = theta[s + 1]; c = theta[s + 2];
    }
    int o = idx * 3;
    gThD[o] = a; gThD[o + 1] = b; gThD[o + 2] = c;
}

__global__ void hmm_clear(const float* __restrict__ A) {
    int t = threadIdx.x;
    if (t < 9)    gB[t] = __expf(A[t]);
    if (t < NBLK) gProg2[t][0] = 0;
}

// ---------------------------------------------------------------- helpers

__device__ __forceinline__ int ld_acq(const int* p) {
    int v;
    asm volatile("ld.acquire.gpu.global.b32 %0, [%1];" : "=r"(v) : "l"(p) : "memory");
    return v;
}
__device__ __forceinline__ void st_rel(int* p, int v) {
    asm volatile("st.release.gpu.global.b32 [%0], %1;" :: "l"(p), "r"(v) : "memory");
}

// ---------------------------------------------------------------- DP kernel

__global__ void __launch_bounds__(HROWS, 1)
hmm_wave(float* __restrict__ out) {
    const int p = blockIdx.x;
    const int l = threadIdx.x;

    const float B00 = gB[0], B01 = gB[1], B02 = gB[2];
    const float B10 = gB[3], B11 = gB[4], B12 = gB[5];
    const float B20 = gB[6], B21 = gB[7], B22 = gB[8];

    // own history h = value of cell (r, j-1); init = column-0 border
    float h_m = NEG_INF, h_e0 = 1.f, h_e1 = 1.f, h_e2 = 1.f;
    // delayed shfl (lane l-1, two steps ago) -> P0 = (i-1, j-1)
    float s_m = NEG_INF, s_e0 = 1.f, s_e1 = 1.f, s_e2 = 1.f;
    // lane0 parent-prev: block0 sees (0,0) = (m=0, e=1,1,1); else col-0 border
    float pp_m = (p == 0) ? 0.f : NEG_INF;
    float pp_e0 = 1.f, pp_e1 = 1.f, pp_e2 = 1.f;

    // lane l of strip p at step t reads gThD[((32p + t - 1)*2048 + 32p + l)*3 ..]
    const int thBase = ((HROWS * p - 1) * MCOLS + HROWS * p + l) * 3;
    const int thStep = MCOLS * 3;   // 6144

    // 8-deep software pipeline
    float4 pq[8];
    float th0[8], th1[8], th2[8];
    const float4* parentRow = gHand[(p > 0) ? (p - 1) : 0];
    const int*    parentFlag = &gProg2[(p > 0) ? (p - 1) : 0][0];

    int avail = 0, availNew = 0;

    #pragma unroll
    for (int k = 0; k < 8; k++) {
        pq[k] = make_float4(NEG_INF, 1.f, 1.f, 1.f);   // block0 P1 = row-0 border
        int off = thBase + (1 + k) * thStep;
        th0[k] = gThD[off]; th1[k] = gThD[off + 1]; th2[k] = gThD[off + 2];
    }
    if (l == 0 && p > 0) {
        while (avail < 8) avail = ld_acq(parentFlag);
        #pragma unroll
        for (int k = 0; k < 8; k++) pq[k] = __ldcg(&parentRow[1 + k]);
        availNew = avail;
    }

    const int TEND = MCOLS + HROWS - 1;   // 2079
    for (int tg = 1; tg <= TEND; tg += 8) {
        // ensure the refills issued THIS group (cols tg+8 .. tg+15) are published
        if (l == 0 && p > 0) {
            if (availNew > avail) avail = availNew;
            int need = tg + 15;
            if (need > MCOLS) need = MCOLS;
            while (avail < need) avail = ld_acq(parentFlag);
            // speculative refresh for the NEXT group; latency hidden under 8 steps
            availNew = ld_acq(parentFlag);
        }
        #pragma unroll
        for (int k = 0; k < 8; k++) {
            const int t = tg + k;
            // consume prefetched values (slot k == (t-1)&7)
            const float t0 = th0[k], t1 = th1[k], t2 = th2[k];
            const float4 P1q = pq[k];
            // refill slot k for step t+8 (availability guaranteed by group-top check)
            {
                const int tp = t + 8;
                if (l == 0 && p > 0 && tp <= MCOLS) pq[k] = __ldcg(&parentRow[tp]);
                int off = thBase + tp * thStep;
                th0[k] = gThD[off]; th1[k] = gThD[off + 1]; th2[k] = gThD[off + 2];
            }
            // lane l-1's step-(t-1) value -> P1 = (i-1, j)
            const float q_m  = __shfl_up_sync(0xffffffffu, h_m, 1);
            const float q_e0 = __shfl_up_sync(0xffffffffu, h_e0, 1);
            const float q_e1 = __shfl_up_sync(0xffffffffu, h_e1, 1);
            const float q_e2 = __shfl_up_sync(0xffffffffu, h_e2, 1);

            float P1m = q_m, P1e0 = q_e0, P1e1 = q_e1, P1e2 = q_e2;
            float P0m = s_m, P0e0 = s_e0, P0e1 = s_e1, P0e2 = s_e2;
            if (l == 0) {                    // parent strip supplies P1 and P0
                P1m = P1q.x; P1e0 = P1q.y; P1e1 = P1q.z; P1e2 = P1q.w;
                P0m = pp_m;  P0e0 = pp_e0; P0e1 = pp_e1; P0e2 = pp_e2;
            }

            // dots: sum_k e_pred[k] * exp(A[s][k])
            const float d0 = fmaf(P0e2, B02, fmaf(P0e1, B01, P0e0 * B00));
            const float d1 = fmaf(P1e2, B12, fmaf(P1e1, B11, P1e0 * B10));
            const float d2 = fmaf(h_e2, B22, fmaf(h_e1, B21, h_e0 * B20));

            const float V0 = t0 + P0m + __logf(d0);
            const float V1 = t1 + P1m + __logf(d1);
            const float V2 = t2 + h_m + __logf(d2);

            const float vm  = fmaxf(V0, fmaxf(V1, V2));
            const float ne0 = __expf(V0 - vm);
            const float ne1 = __expf(V1 - vm);
            const float ne2 = __expf(V2 - vm);

            const bool active = (t > l) && (t <= MCOLS + l);

            // delayed-shfl capture (unconditional register bookkeeping)
            s_m = q_m; s_e0 = q_e0; s_e1 = q_e1; s_e2 = q_e2;

            if (active) {
                h_m = vm; h_e0 = ne0; h_e1 = ne1; h_e2 = ne2;
                if (l == 0) { pp_m = P1m; pp_e0 = P1e0; pp_e1 = P1e1; pp_e2 = P1e2; }
                if (l == HROWS - 1) {
                    __stcg(&gHand[p][t - (HROWS - 1)], make_float4(vm, ne0, ne1, ne2));
                }
            }
        }
        // publish progress once per group (8 columns); release orders data stores first
        if (l == HROWS - 1) {
            int jd = tg + 7 - (HROWS - 1);
            if (jd >= 1) {
                if (jd > MCOLS) jd = MCOLS;
                st_rel(&gProg2[p][0], jd);
            }
        }
    }
    if (l == HROWS - 1) st_rel(&gProg2[p][0], MCOLS);

    // Vt = m + log(e0+e1+e2), held by last strip's bottom lane (cell (2048,2048))
    if (p == NBLK - 1 && l == HROWS - 1)
        out[0] = h_m + __logf(h_e0 + h_e1 + h_e2);
}

extern "C" void kernel_launch(void* const* d_in, const int* in_sizes, int n_in,
                              void* d_out, int out_size) {
    const float* theta = (const float*)d_in[0];
    const float* A     = (const float*)d_in[1];
    float* out = (float*)d_out;
    (void)in_sizes; (void)n_in; (void)out_size;

    diagize<<<(DROWS * MCOLS + 255) / 256, 256>>>(theta);
    hmm_clear<<<1, 256>>>(A);
    hmm_wave<<<NBLK, HROWS>>>(out);
}

// round 15
// speedup vs baseline: 1.4908x; 1.4908x over previous
#include <cuda_runtime.h>
#include <cuda_bf16.h>

// HMM forward DP (softmax semiring).
// 8 blocks x 8 warps; warp = 32-row strip; intra-block handoff via shared-memory
// rings (acquire/release .cta), inter-block via global row + private flag line.
// Numerics identical to R11 (natural log, (m,e) carry), rel_err ~3.6e-6.

#define NEG_INF   (-1.0e8f)
#define MCOLS     2048
#define WPB       8                      /* warps per block  */
#define NBLKS     8                      /* blocks           */
#define RING      128                    /* ring columns     */
#define TEND      (MCOLS + 31)           /* 2079 steps       */
#define DROWSP    4160                   /* padded diagonals */

// diagonal-major theta as float4 (x,y,z = theta[s], w unused):
// gThD4[e * 2048 + u] = theta[u][e-u],  e = i+j-2, u = i-1
__device__ float4 gThD4[(size_t)DROWSP * MCOLS];          // 136 MB
__device__ float4 gHandG[NBLKS][MCOLS + 16];              // inter-block handoff rows
__device__ int    gProgG[NBLKS][32];                      // private flag lines
__device__ float  gB[9];                                  // exp(A[s][k])

// ---------------------------------------------------------------- pre-passes

__global__ void diagize(const float* __restrict__ theta) {
    __shared__ float4 tile[64][33];                       // 33-pad: conflict-free
    const int u0 = blockIdx.x * 64;                       // gridDim.x = 32
    const int e0 = blockIdx.y * 32;                       // gridDim.y = 130
    const int t  = threadIdx.x;                           // 256 threads
    {
        const int eL = t & 31, uB = t >> 5;
        #pragma unroll
        for (int k = 0; k < 8; k++) {
            const int uL = uB * 8 + k;
            const int u = u0 + uL, e = e0 + eL;
            const int c = e - u;                          // theta column
            float4 v = make_float4(0.f, 0.f, 0.f, 0.f);
            if (c >= 0 && c < MCOLS) {
                const int o = (u * MCOLS + c) * 3;
                v.x = theta[o]; v.y = theta[o + 1]; v.z = theta[o + 2];
            }
            tile[uL][eL] = v;
        }
    }
    __syncthreads();
    {
        const int uL = t & 31, eB = t >> 5;
        #pragma unroll
        for (int k = 0; k < 8; k++) {
            const int uL2 = uL + 32 * (k >> 2);
            const int eL2 = eB + 8 * (k & 3);
            gThD4[(size_t)(e0 + eL2) * MCOLS + (u0 + uL2)] = tile[uL2][eL2];
        }
    }
}

__global__ void hmm_clear(const float* __restrict__ A) {
    int t = threadIdx.x;
    if (t < 9)     gB[t] = __expf(A[t]);
    if (t < NBLKS) gProgG[t][0] = 0;
}

// ---------------------------------------------------------------- helpers

__device__ __forceinline__ int ld_acq_gpu(const int* p) {
    int v;
    asm volatile("ld.acquire.gpu.global.b32 %0, [%1];" : "=r"(v) : "l"(p) : "memory");
    return v;
}
__device__ __forceinline__ void st_rel_gpu(int* p, int v) {
    asm volatile("st.release.gpu.global.b32 [%0], %1;" :: "l"(p), "r"(v) : "memory");
}
__device__ __forceinline__ int ld_acq_cta(const int* p) {      // generic addr (shared)
    int v;
    asm volatile("ld.acquire.cta.b32 %0, [%1];" : "=r"(v) : "l"(p) : "memory");
    return v;
}
__device__ __forceinline__ void st_rel_cta(int* p, int v) {
    asm volatile("st.release.cta.b32 [%0], %1;" :: "l"(p), "r"(v) : "memory");
}

// ---------------------------------------------------------------- DP kernel

__global__ void __launch_bounds__(WPB * 32, 1)
hmm_wave(float* __restrict__ out) {
    const int b = blockIdx.x;
    const int w = threadIdx.x >> 5;
    const int l = threadIdx.x & 31;
    const int s = b * WPB + w;                 // strip index 0..63

    __shared__ float4 sRing[WPB - 1][RING];    // 7 * 128 * 16 = 14336 B
    __shared__ int    sProd[WPB - 1][8];
    __shared__ int    sCons[WPB - 1][8];
    if (threadIdx.x < WPB - 1) { sProd[threadIdx.x][0] = 0; sCons[threadIdx.x][0] = 0; }
    __syncthreads();

    const float B00 = gB[0], B01 = gB[1], B02 = gB[2];
    const float B10 = gB[3], B11 = gB[4], B12 = gB[5];
    const float B20 = gB[6], B21 = gB[7], B22 = gB[8];

    // own history h = cell (r, j-1); init = column-0 border
    float h_m = NEG_INF, h_e0 = 1.f, h_e1 = 1.f, h_e2 = 1.f;
    // delayed shfl -> P0 = (i-1, j-1)
    float s_m = NEG_INF, s_e0 = 1.f, s_e1 = 1.f, s_e2 = 1.f;
    // lane0 parent-prev: strip0 sees (0,0)=(m=0,e=1,1,1); else col-0 border
    float pp_m = (s == 0) ? 0.f : NEG_INF;
    float pp_e0 = 1.f, pp_e1 = 1.f, pp_e2 = 1.f;

    const bool isGlobalCons = (w == 0 && b > 0);
    const bool isRingCons   = (w > 0);
    const bool isRingProd   = (w < WPB - 1);
    const bool isGlobalProd = (w == WPB - 1 && b < NBLKS - 1);

    const float4* gH    = gHandG[(b > 0) ? b - 1 : 0];
    const int*    gFlag = &gProgG[(b > 0) ? b - 1 : 0][0];

    // theta: lane l of strip s at step t uses gThD4[(32s + t - 1)*2048 + 32s + l]
    const float4* thPtr = gThD4 + ((long)(32 * s - 1) * MCOLS + 32 * s + l);

    float4 th[8], pq[8];
    #pragma unroll
    for (int k = 0; k < 8; k++) {
        th[k] = __ldcg(&thPtr[(size_t)(1 + k) * MCOLS]);
        pq[k] = make_float4(NEG_INF, 1.f, 1.f, 1.f);      // strip-0 row-0 border
    }
    int avail = 0, availSpec = 0;
    if (isGlobalCons && l == 0) {
        while (avail < 8) avail = ld_acq_gpu(gFlag);
        #pragma unroll
        for (int k = 0; k < 8; k++) pq[k] = __ldcg(&gH[1 + k]);
        availSpec = avail;
    }
    int consSeen = 0;

    for (int tg = 1; tg <= TEND; tg += 8) {
        // ---- group-top waits ----
        if (isGlobalCons && l == 0) {
            if (availSpec > avail) avail = availSpec;
            int need = tg + 15; if (need > MCOLS) need = MCOLS;
            while (avail < need) avail = ld_acq_gpu(gFlag);
            availSpec = ld_acq_gpu(gFlag);     // speculative, hidden under 8 steps
        }
        if (isRingCons && l == 0) {
            int need = tg + 7; if (need > MCOLS) need = MCOLS;
            int pr;
            do { pr = ld_acq_cta(&sProd[w - 1][0]); } while (pr < need);
        }
        if (isRingProd && l == 31) {           // ring space (virtually never trips)
            int jhi = tg + 7 - 31;
            if (jhi >= 1 && jhi > consSeen + (RING - 8)) {
                do { consSeen = *(volatile int*)&sCons[w][0]; }
                while (jhi > consSeen + (RING - 8));
            }
        }
        #pragma unroll
        for (int k = 0; k < 8; k++) {
            const int t = tg + k;
            const float4 tv  = th[k];
            const float4 P1q = pq[k];
            // refill slot k for step t+8
            {
                const int tp = t + 8;
                th[k] = __ldcg(&thPtr[(size_t)tp * MCOLS]);
                if (isGlobalCons && l == 0 && tp <= MCOLS) pq[k] = __ldcg(&gH[tp]);
            }
            // intra-block parent row (lane0 of ring consumers): ~30cy LDS, overlaps shfl
            float4 R1 = P1q;
            if (isRingCons && l == 0) R1 = sRing[w - 1][t & (RING - 1)];

            const float q_m  = __shfl_up_sync(0xffffffffu, h_m, 1);
            const float q_e0 = __shfl_up_sync(0xffffffffu, h_e0, 1);
            const float q_e1 = __shfl_up_sync(0xffffffffu, h_e1, 1);
            const float q_e2 = __shfl_up_sync(0xffffffffu, h_e2, 1);

            float P1m = q_m, P1e0 = q_e0, P1e1 = q_e1, P1e2 = q_e2;
            float P0m = s_m, P0e0 = s_e0, P0e1 = s_e1, P0e2 = s_e2;
            if (l == 0) {
                P1m = R1.x; P1e0 = R1.y; P1e1 = R1.z; P1e2 = R1.w;
                P0m = pp_m; P0e0 = pp_e0; P0e1 = pp_e1; P0e2 = pp_e2;
            }

            const float d0 = fmaf(P0e2, B02, fmaf(P0e1, B01, P0e0 * B00));
            const float d1 = fmaf(P1e2, B12, fmaf(P1e1, B11, P1e0 * B10));
            const float d2 = fmaf(h_e2, B22, fmaf(h_e1, B21, h_e0 * B20));

            const float V0 = tv.x + P0m + __logf(d0);
            const float V1 = tv.y + P1m + __logf(d1);
            const float V2 = tv.z + h_m + __logf(d2);

            const float vm  = fmaxf(V0, fmaxf(V1, V2));
            const float ne0 = __expf(V0 - vm);
            const float ne1 = __expf(V1 - vm);
            const float ne2 = __expf(V2 - vm);

            const bool active = (t > l) && (t <= MCOLS + l);

            s_m = q_m; s_e0 = q_e0; s_e1 = q_e1; s_e2 = q_e2;

            if (active) {
                h_m = vm; h_e0 = ne0; h_e1 = ne1; h_e2 = ne2;
                if (l == 0) { pp_m = P1m; pp_e0 = P1e0; pp_e1 = P1e1; pp_e2 = P1e2; }
                if (l == 31) {
                    const int j = t - 31;                  // 1..2048
                    if (isRingProd)
                        sRing[w][j & (RING - 1)] = make_float4(vm, ne0, ne1, ne2);
                    else if (isGlobalProd)
                        __stcg(&gHandG[b][j], make_float4(vm, ne0, ne1, ne2));
                }
            }
        }
        // ---- group-end publishes ----
        {
            int jd = tg + 7 - 31;
            if (jd >= 1) {
                if (jd > MCOLS) jd = MCOLS;
                if (l == 31) {
                    if (isRingProd)        st_rel_cta(&sProd[w][0], jd);
                    else if (isGlobalProd) st_rel_gpu(&gProgG[b][0], jd);
                }
            }
            if (isRingCons && l == 0) {
                int cd = tg + 7; if (cd > MCOLS) cd = MCOLS;
                *(volatile int*)&sCons[w - 1][0] = cd;     // consumption progress
            }
        }
    }
    if (l == 31) {
        if (isRingProd)        st_rel_cta(&sProd[w][0], MCOLS);
        else if (isGlobalProd) st_rel_gpu(&gProgG[b][0], MCOLS);
    }

    // Vt = m + log(e0+e1+e2), cell (2048, 2048)
    if (b == NBLKS - 1 && w == WPB - 1 && l == 31)
        out[0] = h_m + __logf(h_e0 + h_e1 + h_e2);
}

extern "C" void kernel_launch(void* const* d_in, const int* in_sizes, int n_in,
                              void* d_out, int out_size) {
    const float* theta = (const float*)d_in[0];
    const float* A     = (const float*)d_in[1];
    float* out = (float*)d_out;
    (void)in_sizes; (void)n_in; (void)out_size;

    dim3 dgrid(32, 130);
    diagize<<<dgrid, 256>>>(theta);
    hmm_clear<<<1, 256>>>(A);
    hmm_wave<<<NBLKS, WPB * 32>>>(out);
}

// round 17
// speedup vs baseline: 1.4988x; 1.0054x over previous
#include <cuda_runtime.h>
#include <cuda_bf16.h>

// HMM forward DP (softmax semiring).
// 8 blocks x 8 warps; warp = 32-row strip; intra-block handoff via shared-memory
// rings (acquire/release .cta), inter-block via global row + private flag line.
// Numerics identical to R11 (natural log, (m,e) carry), rel_err ~3.6e-6.

#define NEG_INF   (-1.0e8f)
#define MCOLS     2048
#define WPB       8                      /* warps per block  */
#define NBLKS     8                      /* blocks           */
#define RING      128                    /* ring columns     */
#define TEND      (MCOLS + 31)           /* 2079 steps       */
#define DROWSP    4160                   /* padded diagonals */

// diagonal-major theta as float4 (x,y,z = theta[s], w unused):
// gThD4[e * 2048 + u] = theta[u][e-u],  e = i+j-2, u = i-1
__device__ float4 gThD4[(size_t)DROWSP * MCOLS];          // 136 MB
__device__ float4 gHandG[NBLKS][MCOLS + 16];              // inter-block handoff rows
__device__ int    gProgG[NBLKS][32];                      // private flag lines
__device__ float  gB[9];                                  // exp(A[s][k])

// ---------------------------------------------------------------- pre-passes

__global__ void diagize(const float* __restrict__ theta) {
    __shared__ float4 tile[64][33];                       // 33-pad: conflict-free
    const int u0 = blockIdx.x * 64;                       // gridDim.x = 32
    const int e0 = blockIdx.y * 32;                       // gridDim.y = 130
    const int t  = threadIdx.x;                           // 256 threads
    {
        const int eL = t & 31, uB = t >> 5;
        #pragma unroll
        for (int k = 0; k < 8; k++) {
            const int uL = uB * 8 + k;
            const int u = u0 + uL, e = e0 + eL;
            const int c = e - u;                          // theta column
            float4 v = make_float4(0.f, 0.f, 0.f, 0.f);
            if (c >= 0 && c < MCOLS) {
                const int o = (u * MCOLS + c) * 3;
                v.x = theta[o]; v.y = theta[o + 1]; v.z = theta[o + 2];
            }
            tile[uL][eL] = v;
        }
    }
    __syncthreads();
    {
        const int uL = t & 31, eB = t >> 5;
        #pragma unroll
        for (int k = 0; k < 8; k++) {
            const int uL2 = uL + 32 * (k >> 2);
            const int eL2 = eB + 8 * (k & 3);
            gThD4[(size_t)(e0 + eL2) * MCOLS + (u0 + uL2)] = tile[uL2][eL2];
        }
    }
}

__global__ void hmm_clear(const float* __restrict__ A) {
    int t = threadIdx.x;
    if (t < 9)     gB[t] = __expf(A[t]);
    if (t < NBLKS) gProgG[t][0] = 0;
}

// ---------------------------------------------------------------- helpers

__device__ __forceinline__ int ld_acq_gpu(const int* p) {
    int v;
    asm volatile("ld.acquire.gpu.global.b32 %0, [%1];" : "=r"(v) : "l"(p) : "memory");
    return v;
}
__device__ __forceinline__ void st_rel_gpu(int* p, int v) {
    asm volatile("st.release.gpu.global.b32 [%0], %1;" :: "l"(p), "r"(v) : "memory");
}
__device__ __forceinline__ int ld_acq_cta(const int* p) {      // generic addr (shared)
    int v;
    asm volatile("ld.acquire.cta.b32 %0, [%1];" : "=r"(v) : "l"(p) : "memory");
    return v;
}
__device__ __forceinline__ void st_rel_cta(int* p, int v) {
    asm volatile("st.release.cta.b32 [%0], %1;" :: "l"(p), "r"(v) : "memory");
}

// ---------------------------------------------------------------- DP kernel

__global__ void __launch_bounds__(WPB * 32, 1)
hmm_wave(float* __restrict__ out) {
    const int b = blockIdx.x;
    const int w = threadIdx.x >> 5;
    const int l = threadIdx.x & 31;
    const int s = b * WPB + w;                 // strip index 0..63

    __shared__ float4 sRing[WPB - 1][RING];    // 7 * 128 * 16 = 14336 B
    __shared__ int    sProd[WPB - 1][8];
    __shared__ int    sCons[WPB - 1][8];
    if (threadIdx.x < WPB - 1) { sProd[threadIdx.x][0] = 0; sCons[threadIdx.x][0] = 0; }
    __syncthreads();

    const float B00 = gB[0], B01 = gB[1], B02 = gB[2];
    const float B10 = gB[3], B11 = gB[4], B12 = gB[5];
    const float B20 = gB[6], B21 = gB[7], B22 = gB[8];

    // own history h = cell (r, j-1); init = column-0 border
    float h_m = NEG_INF, h_e0 = 1.f, h_e1 = 1.f, h_e2 = 1.f;
    // delayed shfl -> P0 = (i-1, j-1)
    float s_m = NEG_INF, s_e0 = 1.f, s_e1 = 1.f, s_e2 = 1.f;
    // lane0 parent-prev: strip0 sees (0,0)=(m=0,e=1,1,1); else col-0 border
    float pp_m = (s == 0) ? 0.f : NEG_INF;
    float pp_e0 = 1.f, pp_e1 = 1.f, pp_e2 = 1.f;

    const bool isGlobalCons = (w == 0 && b > 0);
    const bool isRingCons   = (w > 0);
    const bool isRingProd   = (w < WPB - 1);
    const bool isGlobalProd = (w == WPB - 1 && b < NBLKS - 1);

    const float4* gH    = gHandG[(b > 0) ? b - 1 : 0];
    const int*    gFlag = &gProgG[(b > 0) ? b - 1 : 0][0];

    // theta: lane l of strip s at step t uses gThD4[(32s + t - 1)*2048 + 32s + l]
    const float4* thPtr = gThD4 + ((long)(32 * s - 1) * MCOLS + 32 * s + l);

    float4 th[8], pq[8];
    #pragma unroll
    for (int k = 0; k < 8; k++) {
        th[k] = __ldcg(&thPtr[(size_t)(1 + k) * MCOLS]);
        pq[k] = make_float4(NEG_INF, 1.f, 1.f, 1.f);      // strip-0 row-0 border
    }
    int avail = 0, availSpec = 0;
    if (isGlobalCons && l == 0) {
        while (avail < 8) avail = ld_acq_gpu(gFlag);
        #pragma unroll
        for (int k = 0; k < 8; k++) pq[k] = __ldcg(&gH[1 + k]);
        availSpec = avail;
    }
    int consSeen = 0;

    for (int tg = 1; tg <= TEND; tg += 8) {
        // ---- group-top waits ----
        if (isGlobalCons && l == 0) {
            if (availSpec > avail) avail = availSpec;
            int need = tg + 15; if (need > MCOLS) need = MCOLS;
            while (avail < need) avail = ld_acq_gpu(gFlag);
            availSpec = ld_acq_gpu(gFlag);     // speculative, hidden under 8 steps
        }
        if (isRingCons && l == 0) {
            int need = tg + 7; if (need > MCOLS) need = MCOLS;
            int pr;
            do { pr = ld_acq_cta(&sProd[w - 1][0]); } while (pr < need);
        }
        if (isRingProd && l == 31) {           // ring space (virtually never trips)
            int jhi = tg + 7 - 31;
            if (jhi >= 1 && jhi > consSeen + (RING - 8)) {
                do { consSeen = *(volatile int*)&sCons[w][0]; }
                while (jhi > consSeen + (RING - 8));
            }
        }
        #pragma unroll
        for (int k = 0; k < 8; k++) {
            const int t = tg + k;
            const float4 tv  = th[k];
            const float4 P1q = pq[k];
            // refill slot k for step t+8
            {
                const int tp = t + 8;
                th[k] = __ldcg(&thPtr[(size_t)tp * MCOLS]);
                if (isGlobalCons && l == 0 && tp <= MCOLS) pq[k] = __ldcg(&gH[tp]);
            }
            // intra-block parent row (lane0 of ring consumers): ~30cy LDS, overlaps shfl
            float4 R1 = P1q;
            if (isRingCons && l == 0) R1 = sRing[w - 1][t & (RING - 1)];

            const float q_m  = __shfl_up_sync(0xffffffffu, h_m, 1);
            const float q_e0 = __shfl_up_sync(0xffffffffu, h_e0, 1);
            const float q_e1 = __shfl_up_sync(0xffffffffu, h_e1, 1);
            const float q_e2 = __shfl_up_sync(0xffffffffu, h_e2, 1);

            float P1m = q_m, P1e0 = q_e0, P1e1 = q_e1, P1e2 = q_e2;
            float P0m = s_m, P0e0 = s_e0, P0e1 = s_e1, P0e2 = s_e2;
            if (l == 0) {
                P1m = R1.x; P1e0 = R1.y; P1e1 = R1.z; P1e2 = R1.w;
                P0m = pp_m; P0e0 = pp_e0; P0e1 = pp_e1; P0e2 = pp_e2;
            }

            const float d0 = fmaf(P0e2, B02, fmaf(P0e1, B01, P0e0 * B00));
            const float d1 = fmaf(P1e2, B12, fmaf(P1e1, B11, P1e0 * B10));
            const float d2 = fmaf(h_e2, B22, fmaf(h_e1, B21, h_e0 * B20));

            const float V0 = tv.x + P0m + __logf(d0);
            const float V1 = tv.y + P1m + __logf(d1);
            const float V2 = tv.z + h_m + __logf(d2);

            const float vm  = fmaxf(V0, fmaxf(V1, V2));
            const float ne0 = __expf(V0 - vm);
            const float ne1 = __expf(V1 - vm);
            const float ne2 = __expf(V2 - vm);

            const bool active = (t > l) && (t <= MCOLS + l);

            s_m = q_m; s_e0 = q_e0; s_e1 = q_e1; s_e2 = q_e2;

            if (active) {
                h_m = vm; h_e0 = ne0; h_e1 = ne1; h_e2 = ne2;
                if (l == 0) { pp_m = P1m; pp_e0 = P1e0; pp_e1 = P1e1; pp_e2 = P1e2; }
                if (l == 31) {
                    const int j = t - 31;                  // 1..2048
                    if (isRingProd)
                        sRing[w][j & (RING - 1)] = make_float4(vm, ne0, ne1, ne2);
                    else if (isGlobalProd)
                        __stcg(&gHandG[b][j], make_float4(vm, ne0, ne1, ne2));
                }
            }
        }
        // ---- group-end publishes ----
        {
            int jd = tg + 7 - 31;
            if (jd >= 1) {
                if (jd > MCOLS) jd = MCOLS;
                if (l == 31) {
                    if (isRingProd)        st_rel_cta(&sProd[w][0], jd);
                    else if (isGlobalProd) st_rel_gpu(&gProgG[b][0], jd);
                }
            }
            if (isRingCons && l == 0) {
                int cd = tg + 7; if (cd > MCOLS) cd = MCOLS;
                *(volatile int*)&sCons[w - 1][0] = cd;     // consumption progress
            }
        }
    }
    if (l == 31) {
        if (isRingProd)        st_rel_cta(&sProd[w][0], MCOLS);
        else if (isGlobalProd) st_rel_gpu(&gProgG[b][0], MCOLS);
    }

    // Vt = m + log(e0+e1+e2), cell (2048, 2048)
    if (b == NBLKS - 1 && w == WPB - 1 && l == 31)
        out[0] = h_m + __logf(h_e0 + h_e1 + h_e2);
}

extern "C" void kernel_launch(void* const* d_in, const int* in_sizes, int n_in,
                              void* d_out, int out_size) {
    const float* theta = (const float*)d_in[0];
    const float* A     = (const float*)d_in[1];
    float* out = (float*)d_out;
    (void)in_sizes; (void)n_in; (void)out_size;

    dim3 dgrid(32, 130);
    diagize<<<dgrid, 256>>>(theta);
    hmm_clear<<<1, 256>>>(A);
    hmm_wave<<<NBLKS, WPB * 32>>>(out);
}